// round 1
// baseline (speedup 1.0000x reference)
#include <cuda_runtime.h>
#include <cstdint>

// Problem constants
#define BATCH 4
#define SEQ   4096
#define TOK   (BATCH*SEQ)       // 16384
#define DIM   1024
#define FF    4096
#define NEXP  8
#define TOPK  2

#define TM 128
#define TK 16
#define ROW_TILES 264           // capacity tiles: (TOK*TOPK + NEXP*TM)/TM = 264
#define R_CAP (ROW_TILES*TM)    // 33792

// ---------------- scratch (static device globals; no runtime alloc) ----------------
__device__ float g_h[(size_t)R_CAP * FF];     // hidden activations, ~553MB
__device__ int   g_row_token[R_CAP];
__device__ float g_row_gate[R_CAP];
__device__ int   g_tok_e[TOK * TOPK];
__device__ float g_tok_g[TOK * TOPK];
__device__ int   g_counts[NEXP];
__device__ int   g_off[NEXP + 1];
__device__ int   g_cursor[NEXP];

// ---------------- packed f32x2 helpers ----------------
__device__ __forceinline__ unsigned long long pack2(float lo, float hi) {
    unsigned long long r;
    asm("mov.b64 %0, {%1,%2};" : "=l"(r) : "f"(lo), "f"(hi));
    return r;
}
__device__ __forceinline__ void ffma2(unsigned long long& d, unsigned long long a, unsigned long long b) {
    asm("fma.rn.f32x2 %0, %1, %2, %0;" : "+l"(d) : "l"(a), "l"(b));
}
__device__ __forceinline__ float2 unpack2(unsigned long long v) {
    float2 r;
    asm("mov.b64 {%0,%1}, %2;" : "=f"(r.x), "=f"(r.y) : "l"(v));
    return r;
}

// ---------------- init ----------------
__global__ void init_kernel() {
    int i = blockIdx.x * 256 + threadIdx.x;
    if (i < NEXP) g_counts[i] = 0;
    if (i < R_CAP) { g_row_token[i] = 0; g_row_gate[i] = 0.f; }
}

// ---------------- router: logits -> top2 -> gates (softmax denominator cancels) ----------------
__global__ __launch_bounds__(256) void router_kernel(const float* __restrict__ x,
                                                     const float* __restrict__ Wg) {
    __shared__ float sWg[NEXP * DIM];   // transposed: sWg[e*DIM + d]
    int tid = threadIdx.x;
    for (int i = tid; i < NEXP * DIM; i += 256) {
        int d = i & (DIM - 1);
        int e = i >> 10;
        sWg[i] = Wg[d * NEXP + e];
    }
    __syncthreads();
    int warp = tid >> 5, lane = tid & 31;
    int token = blockIdx.x * 8 + warp;
    const float* xr = x + (size_t)token * DIM;
    float acc[NEXP];
#pragma unroll
    for (int e = 0; e < NEXP; e++) acc[e] = 0.f;
    for (int d = lane; d < DIM; d += 32) {
        float xv = xr[d];
#pragma unroll
        for (int e = 0; e < NEXP; e++) acc[e] = fmaf(xv, sWg[e * DIM + d], acc[e]);
    }
#pragma unroll
    for (int e = 0; e < NEXP; e++)
#pragma unroll
        for (int o = 16; o; o >>= 1) acc[e] += __shfl_xor_sync(0xFFFFFFFFu, acc[e], o);
    if (lane == 0) {
        int e0 = 0; float l0 = acc[0];
#pragma unroll
        for (int e = 1; e < NEXP; e++) if (acc[e] > l0) { l0 = acc[e]; e0 = e; }
        int e1 = -1; float l1 = -3.4e38f;
#pragma unroll
        for (int e = 0; e < NEXP; e++) if (e != e0 && acc[e] > l1) { l1 = acc[e]; e1 = e; }
        float g0 = 1.f / (1.f + expf(l1 - l0));
        float g1 = 1.f - g0;
        g_tok_e[token * 2 + 0] = e0;
        g_tok_e[token * 2 + 1] = e1;
        g_tok_g[token * 2 + 0] = g0;
        g_tok_g[token * 2 + 1] = g1;
        atomicAdd(&g_counts[e0], 1);
        atomicAdd(&g_counts[e1], 1);
    }
}

// ---------------- scan: padded segment offsets ----------------
__global__ void scan_kernel() {
    if (threadIdx.x == 0) {
        int off = 0;
        for (int e = 0; e < NEXP; e++) {
            g_off[e] = off;
            g_cursor[e] = off;
            off += ((g_counts[e] + TM - 1) / TM) * TM;
        }
        g_off[NEXP] = off;
    }
}

// ---------------- assign rows to expert segments ----------------
__global__ void assign_kernel() {
    int t = blockIdx.x * 256 + threadIdx.x;
    if (t >= TOK) return;
#pragma unroll
    for (int k = 0; k < TOPK; k++) {
        int e = g_tok_e[t * 2 + k];
        int p = atomicAdd(&g_cursor[e], 1);
        g_row_token[p] = t;
        g_row_gate[p] = g_tok_g[t * 2 + k];
    }
}

// ---------------- zero output ----------------
__global__ void zero_out_kernel(float4* __restrict__ out) {
    int i = blockIdx.x * 256 + threadIdx.x;
    out[i] = make_float4(0.f, 0.f, 0.f, 0.f);
}

// ---------------- GEMM1: h = relu(gather(x) @ W1[e] + b1[e]) ----------------
__global__ __launch_bounds__(256, 2) void gemm1_kernel(const float* __restrict__ x,
                                                       const float* __restrict__ W1,
                                                       const float* __restrict__ b1) {
    __shared__ float As[TK * 132];
    __shared__ float Bs[TK * 128];
    __shared__ int sTok[TM];
    int tid = threadIdx.x;
    int row0 = blockIdx.y * TM;
    int n0 = blockIdx.x * 128;

    int e = 0;
#pragma unroll
    for (int i = 1; i < NEXP; i++) e += (row0 >= g_off[i]) ? 1 : 0;

    if (tid < TM) sTok[tid] = g_row_token[row0 + tid];

    const float* Bp = W1 + (size_t)e * DIM * FF + n0;
    const float* bias = b1 + e * FF + n0;

    int ty = tid >> 4, tx = tid & 15;
    unsigned long long acc[8][4];
#pragma unroll
    for (int i = 0; i < 8; i++)
#pragma unroll
        for (int j = 0; j < 4; j++) acc[i][j] = 0ull;

    for (int kt = 0; kt < DIM / TK; kt++) {
        __syncthreads();
#pragma unroll
        for (int i = 0; i < 2; i++) {
            int f = tid + i * 256;
            int m = f >> 2, kq = (f & 3) << 2;
            const float4 v = *(const float4*)(x + (size_t)sTok[m] * DIM + kt * TK + kq);
            As[(kq + 0) * 132 + m] = v.x;
            As[(kq + 1) * 132 + m] = v.y;
            As[(kq + 2) * 132 + m] = v.z;
            As[(kq + 3) * 132 + m] = v.w;
            int k = f >> 5, nq = (f & 31) << 2;
            *(float4*)&Bs[k * 128 + nq] = *(const float4*)(Bp + (size_t)(kt * TK + k) * FF + nq);
        }
        __syncthreads();
#pragma unroll
        for (int k = 0; k < TK; k++) {
            float4 a0 = *(float4*)&As[k * 132 + ty * 8];
            float4 a1 = *(float4*)&As[k * 132 + ty * 8 + 4];
            ulonglong2 bl0 = *(ulonglong2*)&Bs[k * 128 + tx * 8];
            ulonglong2 bl1 = *(ulonglong2*)&Bs[k * 128 + tx * 8 + 4];
            unsigned long long a2[8], b2[4];
            a2[0] = pack2(a0.x, a0.x); a2[1] = pack2(a0.y, a0.y);
            a2[2] = pack2(a0.z, a0.z); a2[3] = pack2(a0.w, a0.w);
            a2[4] = pack2(a1.x, a1.x); a2[5] = pack2(a1.y, a1.y);
            a2[6] = pack2(a1.z, a1.z); a2[7] = pack2(a1.w, a1.w);
            b2[0] = bl0.x; b2[1] = bl0.y; b2[2] = bl1.x; b2[3] = bl1.y;
#pragma unroll
            for (int i = 0; i < 8; i++)
#pragma unroll
                for (int j = 0; j < 4; j++) ffma2(acc[i][j], a2[i], b2[j]);
        }
    }

#pragma unroll
    for (int i = 0; i < 8; i++) {
        int r = row0 + ty * 8 + i;
        float* hp = g_h + (size_t)r * FF + n0 + tx * 8;
        float ot[8];
#pragma unroll
        for (int j = 0; j < 4; j++) {
            float2 v = unpack2(acc[i][j]);
            ot[2 * j] = v.x; ot[2 * j + 1] = v.y;
        }
#pragma unroll
        for (int jj = 0; jj < 8; jj++)
            ot[jj] = fmaxf(ot[jj] + bias[tx * 8 + jj], 0.f);
        *(float4*)hp = make_float4(ot[0], ot[1], ot[2], ot[3]);
        *(float4*)(hp + 4) = make_float4(ot[4], ot[5], ot[6], ot[7]);
    }
}

// ---------------- GEMM2: out[token] += gate * (h @ W2[e] + b2[e]) ----------------
__global__ __launch_bounds__(256, 2) void gemm2_kernel(const float* __restrict__ W2,
                                                       const float* __restrict__ b2,
                                                       float* __restrict__ out) {
    __shared__ float As[TK * 132];
    __shared__ float Bs[TK * 128];
    __shared__ int sTok[TM];
    __shared__ float sGate[TM];
    int tid = threadIdx.x;
    int row0 = blockIdx.y * TM;
    int n0 = blockIdx.x * 128;

    int e = 0;
#pragma unroll
    for (int i = 1; i < NEXP; i++) e += (row0 >= g_off[i]) ? 1 : 0;

    if (tid < TM) {
        sTok[tid] = g_row_token[row0 + tid];
        sGate[tid] = g_row_gate[row0 + tid];
    }

    const float* Bp = W2 + (size_t)e * FF * DIM + n0;
    const float* bias = b2 + e * DIM + n0;

    int ty = tid >> 4, tx = tid & 15;
    unsigned long long acc[8][4];
#pragma unroll
    for (int i = 0; i < 8; i++)
#pragma unroll
        for (int j = 0; j < 4; j++) acc[i][j] = 0ull;

    for (int kt = 0; kt < FF / TK; kt++) {
        __syncthreads();
#pragma unroll
        for (int i = 0; i < 2; i++) {
            int f = tid + i * 256;
            int m = f >> 2, kq = (f & 3) << 2;
            const float4 v = *(const float4*)(g_h + (size_t)(row0 + m) * FF + kt * TK + kq);
            As[(kq + 0) * 132 + m] = v.x;
            As[(kq + 1) * 132 + m] = v.y;
            As[(kq + 2) * 132 + m] = v.z;
            As[(kq + 3) * 132 + m] = v.w;
            int k = f >> 5, nq = (f & 31) << 2;
            *(float4*)&Bs[k * 128 + nq] = *(const float4*)(Bp + (size_t)(kt * TK + k) * DIM + nq);
        }
        __syncthreads();
#pragma unroll
        for (int k = 0; k < TK; k++) {
            float4 a0 = *(float4*)&As[k * 132 + ty * 8];
            float4 a1 = *(float4*)&As[k * 132 + ty * 8 + 4];
            ulonglong2 bl0 = *(ulonglong2*)&Bs[k * 128 + tx * 8];
            ulonglong2 bl1 = *(ulonglong2*)&Bs[k * 128 + tx * 8 + 4];
            unsigned long long a2[8], b2r[4];
            a2[0] = pack2(a0.x, a0.x); a2[1] = pack2(a0.y, a0.y);
            a2[2] = pack2(a0.z, a0.z); a2[3] = pack2(a0.w, a0.w);
            a2[4] = pack2(a1.x, a1.x); a2[5] = pack2(a1.y, a1.y);
            a2[6] = pack2(a1.z, a1.z); a2[7] = pack2(a1.w, a1.w);
            b2r[0] = bl0.x; b2r[1] = bl0.y; b2r[2] = bl1.x; b2r[3] = bl1.y;
#pragma unroll
            for (int i = 0; i < 8; i++)
#pragma unroll
                for (int j = 0; j < 4; j++) ffma2(acc[i][j], a2[i], b2r[j]);
        }
    }

#pragma unroll
    for (int i = 0; i < 8; i++) {
        int lr = ty * 8 + i;
        int token = sTok[lr];
        float g = sGate[lr];
        float* op = out + (size_t)token * DIM + n0 + tx * 8;
#pragma unroll
        for (int j = 0; j < 4; j++) {
            float2 v = unpack2(acc[i][j]);
            float v0 = (v.x + bias[tx * 8 + 2 * j]) * g;
            float v1 = (v.y + bias[tx * 8 + 2 * j + 1]) * g;
            atomicAdd(op + 2 * j, v0);
            atomicAdd(op + 2 * j + 1, v1);
        }
    }
}

// ---------------- launch ----------------
extern "C" void kernel_launch(void* const* d_in, const int* in_sizes, int n_in,
                              void* d_out, int out_size) {
    const float* x  = (const float*)d_in[0];
    const float* Wg = (const float*)d_in[1];
    const float* W1 = (const float*)d_in[2];
    const float* b1 = (const float*)d_in[3];
    const float* W2 = (const float*)d_in[4];
    const float* b2 = (const float*)d_in[5];
    float* out = (float*)d_out;

    init_kernel<<<R_CAP / 256, 256>>>();
    router_kernel<<<TOK / 8, 256>>>(x, Wg);
    scan_kernel<<<1, 32>>>();
    assign_kernel<<<TOK / 256, 256>>>();
    zero_out_kernel<<<(TOK * DIM / 4) / 256, 256>>>((float4*)out);
    gemm1_kernel<<<dim3(FF / 128, ROW_TILES), 256>>>(x, W1, b1);
    gemm2_kernel<<<dim3(DIM / 128, ROW_TILES), 256>>>(W2, b2, out);
}

// round 3
// speedup vs baseline: 3.6629x; 3.6629x over previous
#include <cuda_runtime.h>
#include <cstdint>

// ---------------- problem constants ----------------
#define TOK   16384
#define DIMD  1024
#define FF    4096
#define NEXP  8
#define TM    128
#define TN    256
#define KT    32
#define ROW_TILES 264
#define R_CAP (ROW_TILES*TM)     // 33792

// smem layout (floats): A stages 3*4096, B stages 3*8448
#define A_STAGE 4096
#define B_STAGE 8448
#define SMEM_FLOATS (3*A_STAGE + 3*B_STAGE)
#define SMEM_BYTES  (SMEM_FLOATS*4)

// ---------------- device scratch ----------------
__device__ float g_xg[(size_t)R_CAP * DIMD];            // gathered, tf32-rounded
__device__ float g_h[(size_t)R_CAP * FF];               // hidden, tf32-rounded
__device__ float g_y[(size_t)R_CAP * DIMD];             // gemm2 raw output
__device__ float g_w1r[(size_t)NEXP * DIMD * FF];       // tf32-rounded W1 [e][d][f]
__device__ float g_w2r[(size_t)NEXP * FF * DIMD];       // tf32-rounded W2 [e][f][d]

__device__ int   g_row_token[R_CAP];
__device__ int   g_tok_e[TOK * 2];
__device__ float g_tok_g[TOK * 2];
__device__ int   g_tok_row[TOK * 2];
__device__ int   g_counts[NEXP];
__device__ int   g_off[NEXP + 1];
__device__ int   g_cursor[NEXP];

// ---------------- helpers ----------------
__device__ __forceinline__ uint32_t smem_u32(const void* p) {
    uint32_t a;
    asm("{ .reg .u64 t; cvta.to.shared.u64 t, %1; cvt.u32.u64 %0, t; }" : "=r"(a) : "l"(p));
    return a;
}
__device__ __forceinline__ void cp_async16(uint32_t dst, const void* src) {
    asm volatile("cp.async.cg.shared.global [%0], [%1], 16;" :: "r"(dst), "l"(src));
}
#define CP_COMMIT() asm volatile("cp.async.commit_group;" ::: "memory")
#define CP_WAIT1()  asm volatile("cp.async.wait_group 1;" ::: "memory")
#define CP_WAIT0()  asm volatile("cp.async.wait_group 0;" ::: "memory")

__device__ __forceinline__ float to_tf32(float x) {
    uint32_t r;
    asm("cvt.rna.tf32.f32 %0, %1;" : "=r"(r) : "f"(x));
    return __uint_as_float(r);
}
__device__ __forceinline__ void mma_tf32(float* d,
    uint32_t a0, uint32_t a1, uint32_t a2, uint32_t a3,
    uint32_t b0, uint32_t b1) {
    asm volatile("mma.sync.aligned.m16n8k8.row.col.f32.tf32.tf32.f32 "
        "{%0,%1,%2,%3}, {%4,%5,%6,%7}, {%8,%9}, {%0,%1,%2,%3};"
        : "+f"(d[0]), "+f"(d[1]), "+f"(d[2]), "+f"(d[3])
        : "r"(a0), "r"(a1), "r"(a2), "r"(a3), "r"(b0), "r"(b1));
}

// ---------------- routing kernels ----------------
__global__ void init_kernel() {
    int i = blockIdx.x * 256 + threadIdx.x;
    if (i < NEXP) g_counts[i] = 0;
    if (i < R_CAP) g_row_token[i] = 0;
}

__global__ __launch_bounds__(256) void router_kernel(const float* __restrict__ x,
                                                     const float* __restrict__ Wg) {
    __shared__ float sWg[NEXP * DIMD];
    int tid = threadIdx.x;
    for (int i = tid; i < NEXP * DIMD; i += 256) {
        int d = i & (DIMD - 1);
        int e = i >> 10;
        sWg[i] = Wg[d * NEXP + e];
    }
    __syncthreads();
    int warp = tid >> 5, lane = tid & 31;
    int token = blockIdx.x * 8 + warp;
    const float* xr = x + (size_t)token * DIMD;
    float acc[NEXP];
#pragma unroll
    for (int e = 0; e < NEXP; e++) acc[e] = 0.f;
    for (int d = lane; d < DIMD; d += 32) {
        float xv = xr[d];
#pragma unroll
        for (int e = 0; e < NEXP; e++) acc[e] = fmaf(xv, sWg[e * DIMD + d], acc[e]);
    }
#pragma unroll
    for (int e = 0; e < NEXP; e++)
#pragma unroll
        for (int o = 16; o; o >>= 1) acc[e] += __shfl_xor_sync(0xFFFFFFFFu, acc[e], o);
    if (lane == 0) {
        int e0 = 0; float l0 = acc[0];
#pragma unroll
        for (int e = 1; e < NEXP; e++) if (acc[e] > l0) { l0 = acc[e]; e0 = e; }
        int e1 = -1; float l1 = -3.4e38f;
#pragma unroll
        for (int e = 0; e < NEXP; e++) if (e != e0 && acc[e] > l1) { l1 = acc[e]; e1 = e; }
        float g0 = 1.f / (1.f + expf(l1 - l0));
        g_tok_e[token * 2 + 0] = e0;
        g_tok_e[token * 2 + 1] = e1;
        g_tok_g[token * 2 + 0] = g0;
        g_tok_g[token * 2 + 1] = 1.f - g0;
        atomicAdd(&g_counts[e0], 1);
        atomicAdd(&g_counts[e1], 1);
    }
}

__global__ void scan_kernel() {
    if (threadIdx.x == 0) {
        int off = 0;
        for (int e = 0; e < NEXP; e++) {
            g_off[e] = off;
            g_cursor[e] = off;
            off += ((g_counts[e] + TM - 1) / TM) * TM;
        }
        g_off[NEXP] = off;
    }
}

__global__ void assign_kernel() {
    int t = blockIdx.x * 256 + threadIdx.x;
    if (t >= TOK) return;
#pragma unroll
    for (int k = 0; k < 2; k++) {
        int e = g_tok_e[t * 2 + k];
        int p = atomicAdd(&g_cursor[e], 1);
        g_row_token[p] = t;
        g_tok_row[t * 2 + k] = p;
    }
}

// gather x rows (padded segments), round to tf32
__global__ __launch_bounds__(256) void gather_x_kernel(const float* __restrict__ x) {
    size_t base = ((size_t)blockIdx.x * 256 + threadIdx.x) * 4;
    int row = (int)(base >> 10);
    int col = (int)(base & 1023);
    int tok = g_row_token[row];
    float4 v = *(const float4*)(x + (size_t)tok * DIMD + col);
    v.x = to_tf32(v.x); v.y = to_tf32(v.y); v.z = to_tf32(v.z); v.w = to_tf32(v.w);
    *(float4*)(g_xg + base) = v;
}

// elementwise tf32 rounding for weights
__global__ __launch_bounds__(256) void round_w_kernel(const float* __restrict__ src,
                                                      float* __restrict__ dst) {
    size_t i = ((size_t)blockIdx.x * 256 + threadIdx.x) * 4;
    float4 v = *(const float4*)(src + i);
    v.x = to_tf32(v.x); v.y = to_tf32(v.y); v.z = to_tf32(v.z); v.w = to_tf32(v.w);
    *(float4*)(dst + i) = v;
}

// ---------------- tf32 mma mainloop (shared by both GEMMs) ----------------
struct Frag { float acc[4][8][4]; };

__device__ __forceinline__ void load_tile(float* As, float* Bs, int s, int kt,
                                          const float* Agm, int lda,
                                          const float* Bgm, int ldb, int tid) {
#pragma unroll
    for (int i = 0; i < 4; i++) {           // A: 128 rows x 32 floats = 1024 chunks
        int c = tid + i * 256;
        int r = c >> 3, ch = c & 7;
        uint32_t dst = smem_u32(&As[s * A_STAGE + r * 32 + ((ch ^ (r & 7)) << 2)]);
        cp_async16(dst, Agm + (size_t)r * lda + kt * KT + ch * 4);
    }
#pragma unroll
    for (int i = 0; i < 8; i++) {           // B: 32 k-rows x 256 floats = 2048 chunks
        int c = tid + i * 256;
        int kr = c >> 6, ch = c & 63;
        uint32_t dst = smem_u32(&Bs[s * B_STAGE + kr * 264 + ch * 4]);
        cp_async16(dst, Bgm + (size_t)(kt * KT + kr) * ldb + ch * 4);
    }
}

__device__ __forceinline__ void gemm_mainloop(Frag& F, float* As, float* Bs,
                                              const float* Agm, int lda,
                                              const float* Bgm, int ldb,
                                              int ktiles, int tid) {
    int lane = tid & 31, wid = tid >> 5;
    int warp_m = wid & 1, warp_n = wid >> 1;
    int gid = lane >> 2, tig = lane & 3;

    int arow[4], bcol[8];
#pragma unroll
    for (int mt = 0; mt < 4; mt++) arow[mt] = (warp_m * 64 + mt * 16 + gid) * 32 + tig;
#pragma unroll
    for (int nt = 0; nt < 8; nt++) bcol[nt] = warp_n * 64 + nt * 8 + gid;

#pragma unroll
    for (int mt = 0; mt < 4; mt++)
#pragma unroll
        for (int nt = 0; nt < 8; nt++)
#pragma unroll
            for (int q = 0; q < 4; q++) F.acc[mt][nt][q] = 0.f;

    load_tile(As, Bs, 0, 0, Agm, lda, Bgm, ldb, tid); CP_COMMIT();
    load_tile(As, Bs, 1, 1, Agm, lda, Bgm, ldb, tid); CP_COMMIT();

    for (int kt = 0; kt < ktiles; kt++) {
        int s = kt % 3;
        CP_WAIT1();
        __syncthreads();
        int ktn = kt + 2;
        if (ktn < ktiles)
            load_tile(As, Bs, ktn % 3, ktn, Agm, lda, Bgm, ldb, tid);
        CP_COMMIT();

        const float* as = As + s * A_STAGE;
        const float* bs = Bs + s * B_STAGE;
#pragma unroll
        for (int ks = 0; ks < 4; ks++) {
            int ax = ((2 * ks) ^ gid) << 2;
            uint32_t af[4][4];
#pragma unroll
            for (int mt = 0; mt < 4; mt++) {
                af[mt][0] = __float_as_uint(as[arow[mt] + ax]);
                af[mt][1] = __float_as_uint(as[arow[mt] + ax + 256]);
                af[mt][2] = __float_as_uint(as[arow[mt] + (ax ^ 4)]);
                af[mt][3] = __float_as_uint(as[arow[mt] + (ax ^ 4) + 256]);
            }
            int kb0 = (8 * ks + tig) * 264;
            uint32_t bf[8][2];
#pragma unroll
            for (int nt = 0; nt < 8; nt++) {
                bf[nt][0] = __float_as_uint(bs[kb0 + bcol[nt]]);
                bf[nt][1] = __float_as_uint(bs[kb0 + 4 * 264 + bcol[nt]]);
            }
#pragma unroll
            for (int mt = 0; mt < 4; mt++)
#pragma unroll
                for (int nt = 0; nt < 8; nt++)
                    mma_tf32(F.acc[mt][nt], af[mt][0], af[mt][1], af[mt][2], af[mt][3],
                             bf[nt][0], bf[nt][1]);
        }
    }
    CP_WAIT0();
}

// ---------------- GEMM1: h = tf32(relu(xg @ W1[e] + b1[e])) ----------------
__global__ __launch_bounds__(256, 1) void gemm1_kernel(const float* __restrict__ b1) {
    extern __shared__ float sm[];
    float* As = sm;
    float* Bs = sm + 3 * A_STAGE;
    int tid = threadIdx.x;
    int row0 = blockIdx.x * TM;
    int n0 = blockIdx.y * TN;
    int e = 0;
#pragma unroll
    for (int i = 1; i < NEXP; i++) e += (row0 >= g_off[i]) ? 1 : 0;

    const float* Agm = g_xg + (size_t)row0 * DIMD;
    const float* Bgm = g_w1r + (size_t)e * DIMD * FF + n0;

    Frag F;
    gemm_mainloop(F, As, Bs, Agm, DIMD, Bgm, FF, DIMD / KT, tid);

    int lane = tid & 31, wid = tid >> 5;
    int warp_m = wid & 1, warp_n = wid >> 1;
    int gid = lane >> 2, tig = lane & 3;
    const float* bias = b1 + e * FF + n0;

#pragma unroll
    for (int nt = 0; nt < 8; nt++) {
        int gc = warp_n * 64 + nt * 8 + tig * 2;
        float bv0 = __ldg(bias + gc), bv1 = __ldg(bias + gc + 1);
#pragma unroll
        for (int mt = 0; mt < 4; mt++) {
            int gr0 = row0 + warp_m * 64 + mt * 16 + gid;
            float2 v0, v1;
            v0.x = to_tf32(fmaxf(F.acc[mt][nt][0] + bv0, 0.f));
            v0.y = to_tf32(fmaxf(F.acc[mt][nt][1] + bv1, 0.f));
            v1.x = to_tf32(fmaxf(F.acc[mt][nt][2] + bv0, 0.f));
            v1.y = to_tf32(fmaxf(F.acc[mt][nt][3] + bv1, 0.f));
            *(float2*)(g_h + (size_t)gr0 * FF + n0 + gc) = v0;
            *(float2*)(g_h + (size_t)(gr0 + 8) * FF + n0 + gc) = v1;
        }
    }
}

// ---------------- GEMM2: y = h @ W2[e]  (bias+gate applied in combine) ----------------
__global__ __launch_bounds__(256, 1) void gemm2_kernel() {
    extern __shared__ float sm[];
    float* As = sm;
    float* Bs = sm + 3 * A_STAGE;
    int tid = threadIdx.x;
    int row0 = blockIdx.x * TM;
    int n0 = blockIdx.y * TN;
    int e = 0;
#pragma unroll
    for (int i = 1; i < NEXP; i++) e += (row0 >= g_off[i]) ? 1 : 0;

    const float* Agm = g_h + (size_t)row0 * FF;
    const float* Bgm = g_w2r + (size_t)e * FF * DIMD + n0;

    Frag F;
    gemm_mainloop(F, As, Bs, Agm, FF, Bgm, DIMD, FF / KT, tid);

    int lane = tid & 31, wid = tid >> 5;
    int warp_m = wid & 1, warp_n = wid >> 1;
    int gid = lane >> 2, tig = lane & 3;

#pragma unroll
    for (int nt = 0; nt < 8; nt++) {
        int gc = warp_n * 64 + nt * 8 + tig * 2;
#pragma unroll
        for (int mt = 0; mt < 4; mt++) {
            int gr0 = row0 + warp_m * 64 + mt * 16 + gid;
            float2 v0 = { F.acc[mt][nt][0], F.acc[mt][nt][1] };
            float2 v1 = { F.acc[mt][nt][2], F.acc[mt][nt][3] };
            *(float2*)(g_y + (size_t)gr0 * DIMD + n0 + gc) = v0;
            *(float2*)(g_y + (size_t)(gr0 + 8) * DIMD + n0 + gc) = v1;
        }
    }
}

// ---------------- combine: out[t] = sum_k g_k*(y[row_k] + b2[e_k]) ----------------
__global__ __launch_bounds__(256) void combine_kernel(const float* __restrict__ b2,
                                                      float* __restrict__ out) {
    int t = blockIdx.x;
    int d = threadIdx.x * 4;
    int r0 = g_tok_row[t * 2], r1 = g_tok_row[t * 2 + 1];
    int e0 = g_tok_e[t * 2],   e1 = g_tok_e[t * 2 + 1];
    float gg0 = g_tok_g[t * 2], gg1 = g_tok_g[t * 2 + 1];
    float4 y0 = *(const float4*)(g_y + (size_t)r0 * DIMD + d);
    float4 y1 = *(const float4*)(g_y + (size_t)r1 * DIMD + d);
    float4 bA = *(const float4*)(b2 + (size_t)e0 * DIMD + d);
    float4 bB = *(const float4*)(b2 + (size_t)e1 * DIMD + d);
    float4 o;
    o.x = gg0 * (y0.x + bA.x) + gg1 * (y1.x + bB.x);
    o.y = gg0 * (y0.y + bA.y) + gg1 * (y1.y + bB.y);
    o.z = gg0 * (y0.z + bA.z) + gg1 * (y1.z + bB.z);
    o.w = gg0 * (y0.w + bA.w) + gg1 * (y1.w + bB.w);
    *(float4*)(out + (size_t)t * DIMD + d) = o;
}

// ---------------- host launch ----------------
extern "C" void kernel_launch(void* const* d_in, const int* in_sizes, int n_in,
                              void* d_out, int out_size) {
    const float* x  = (const float*)d_in[0];
    const float* Wg = (const float*)d_in[1];
    const float* W1 = (const float*)d_in[2];
    const float* b1 = (const float*)d_in[3];
    const float* W2 = (const float*)d_in[4];
    const float* b2 = (const float*)d_in[5];
    float* out = (float*)d_out;

    static int smem_set = 0;
    // setting attributes is idempotent and capture-safe? -> do unconditionally via
    // cudaFuncSetAttribute each call (it is a host-side setting, not a stream op).
    cudaFuncSetAttribute(gemm1_kernel, cudaFuncAttributeMaxDynamicSharedMemorySize, SMEM_BYTES);
    cudaFuncSetAttribute(gemm2_kernel, cudaFuncAttributeMaxDynamicSharedMemorySize, SMEM_BYTES);
    (void)smem_set;

    float *pW1r, *pW2r;
    cudaGetSymbolAddress((void**)&pW1r, g_w1r);
    cudaGetSymbolAddress((void**)&pW2r, g_w2r);

    init_kernel<<<R_CAP / 256, 256>>>();
    router_kernel<<<TOK / 8, 256>>>(x, Wg);
    scan_kernel<<<1, 32>>>();
    assign_kernel<<<TOK / 256, 256>>>();
    gather_x_kernel<<<(R_CAP * (DIMD / 4)) / 256, 256>>>(x);
    round_w_kernel<<<(NEXP * DIMD * FF / 4) / 256, 256>>>(W1, pW1r);
    round_w_kernel<<<(NEXP * FF * DIMD / 4) / 256, 256>>>(W2, pW2r);
    gemm1_kernel<<<dim3(ROW_TILES, FF / TN), 256, SMEM_BYTES>>>(b1);
    gemm2_kernel<<<dim3(ROW_TILES, DIMD / TN), 256, SMEM_BYTES>>>();
    combine_kernel<<<TOK, 256>>>(b2, out);
}